// round 13
// baseline (speedup 1.0000x reference)
#include <cuda_runtime.h>
#include <cuda_bf16.h>
#include <cstdint>

// Problem constants
#define S_DIM 128
#define I_DIM 384
#define IN_D  256
#define PD    32
#define OD    128

// Scratch (static device globals)
__device__ __nv_bfloat16 g_Lsp[12288 * 256];  // [id][ Lh(128) | Ll(128) ]
__device__ __nv_bfloat16 g_Rsp[12288 * 256];  // [je][ Rh | Rl ]
__device__ __nv_bfloat16 g_Wt [128 * 2048];   // [f ][ Wh(1024) | Wl(1024) ]
__device__ float         g_norm[I_DIM * I_DIM];

// ---------------------------------------------------------------------------
// helpers
// ---------------------------------------------------------------------------
__device__ __forceinline__ uint32_t smem_u32(const void* p) {
    uint32_t a;
    asm("{ .reg .u64 t; cvta.to.shared.u64 t, %1; cvt.u32.u64 %0, t; }"
        : "=r"(a) : "l"(p));
    return a;
}
__device__ __forceinline__ void ldsm_x4(uint32_t* r, uint32_t addr) {
    asm volatile("ldmatrix.sync.aligned.m8n8.x4.shared.b16 {%0,%1,%2,%3}, [%4];"
                 : "=r"(r[0]), "=r"(r[1]), "=r"(r[2]), "=r"(r[3]) : "r"(addr));
}
__device__ __forceinline__ void mma2(float* d, const uint32_t* a,
                                     uint32_t b0, uint32_t b1) {
    asm volatile(
        "mma.sync.aligned.m16n8k16.row.col.f32.bf16.bf16.f32 "
        "{%0,%1,%2,%3}, {%4,%5,%6,%7}, {%8,%9}, {%0,%1,%2,%3};"
        : "+f"(d[0]), "+f"(d[1]), "+f"(d[2]), "+f"(d[3])
        : "r"(a[0]), "r"(a[1]), "r"(a[2]), "r"(a[3]), "r"(b0), "r"(b1));
}
__device__ __forceinline__ void bsplit(float v, __nv_bfloat16& h, __nv_bfloat16& l) {
    h = __float2bfloat16(v);
    l = __float2bfloat16(v - __bfloat162float(h));
}
__device__ __forceinline__ void cpa16(uint32_t s, const void* g) {
    asm volatile("cp.async.cg.shared.global [%0], [%1], 16;" :: "r"(s), "l"(g));
}
#define CPA_COMMIT() asm volatile("cp.async.commit_group;" ::: "memory")
#define CPA_WAIT1()  asm volatile("cp.async.wait_group 1;" ::: "memory")
#define CPA_WAIT0()  asm volatile("cp.async.wait_group 0;" ::: "memory")

// ---------------------------------------------------------------------------
// Kernel A: LayerNorm + projection + mask -> split-bf16 scratch
// ---------------------------------------------------------------------------
__global__ __launch_bounds__(256) void ln_proj_kernel(
    const float* __restrict__ node, const float* __restrict__ mask,
    const float* __restrict__ Wp,   const float* __restrict__ bp)
{
    extern __shared__ float sm[];
    float* Wt_s = sm;            // 64 rows x 260 floats
    float* xs   = sm + 16640;    // 8 x 256 floats

    int t = threadIdx.x;
    for (int v = t; v < 16384; v += 256) {
        int k = v >> 6, c = v & 63;
        Wt_s[c * 260 + k] = Wp[v];
    }

    int w = t >> 5, lane = t & 31;
    int row = blockIdx.x * 8 + w;
    const float* xr = node + (size_t)row * IN_D;

    float xv[8], s1 = 0.f, s2 = 0.f;
#pragma unroll
    for (int u = 0; u < 8; u++) {
        xv[u] = xr[lane + 32 * u];
        s1 += xv[u];
        s2 += xv[u] * xv[u];
    }
#pragma unroll
    for (int off = 16; off > 0; off >>= 1) {
        s1 += __shfl_xor_sync(0xffffffffu, s1, off);
        s2 += __shfl_xor_sync(0xffffffffu, s2, off);
    }
    float mu  = s1 * (1.f / IN_D);
    float var = s2 * (1.f / IN_D) - mu * mu;
    float rs  = rsqrtf(var + 1e-5f);

    float* xrow = xs + w * 256;
#pragma unroll
    for (int u = 0; u < 8; u++) xrow[lane + 32 * u] = (xv[u] - mu) * rs;
    __syncthreads();

    const float4* wr0 = (const float4*)(Wt_s + lane * 260);
    const float4* wr1 = (const float4*)(Wt_s + (lane + 32) * 260);
    const float4* xr4 = (const float4*)xrow;
    float a0 = 0.f, a1 = 0.f;
#pragma unroll 8
    for (int k4 = 0; k4 < 64; k4++) {
        float4 xk = xr4[k4];
        float4 w0 = wr0[k4];
        float4 w1 = wr1[k4];
        a0 = fmaf(xk.x, w0.x, a0); a0 = fmaf(xk.y, w0.y, a0);
        a0 = fmaf(xk.z, w0.z, a0); a0 = fmaf(xk.w, w0.w, a0);
        a1 = fmaf(xk.x, w1.x, a1); a1 = fmaf(xk.y, w1.y, a1);
        a1 = fmaf(xk.z, w1.z, a1); a1 = fmaf(xk.w, w1.w, a1);
    }
    float m  = mask[row];
    int  si  = row / I_DIM, ii = row % I_DIM;
    float lv = (a0 + bp[lane])      * m;
    float rv = (a1 + bp[lane + 32]) * m;

    __nv_bfloat16 lh, ll, rh, rl;
    bsplit(lv, lh, ll);
    bsplit(rv, rh, rl);

    size_t rb = (size_t)(ii * 32 + lane) * 256;
    g_Lsp[rb + si]       = lh;
    g_Lsp[rb + 128 + si] = ll;
    g_Rsp[rb + si]       = rh;
    g_Rsp[rb + 128 + si] = rl;
}

// ---------------------------------------------------------------------------
// Kernel B: norm Gram
// ---------------------------------------------------------------------------
__global__ __launch_bounds__(256) void norm_kernel(const float* __restrict__ mask)
{
    int idx = blockIdx.x * 256 + threadIdx.x;
    int i = idx / I_DIM, j = idx % I_DIM;
    float s = 0.f;
#pragma unroll 4
    for (int ss = 0; ss < S_DIM; ss++)
        s = fmaf(mask[ss * I_DIM + i], mask[ss * I_DIM + j], s);
    g_norm[idx] = s;
}

// ---------------------------------------------------------------------------
// Kernel B2: transpose + split out_weights -> g_Wt [f][ Wh | Wl ]
// ---------------------------------------------------------------------------
__global__ __launch_bounds__(256) void wprep_kernel(const float* __restrict__ W2)
{
    int idx = blockIdx.x * 256 + threadIdx.x;   // < 131072
    int f = idx >> 10, k = idx & 1023;
    float v = W2[k * 128 + f];
    __nv_bfloat16 h, lo;
    bsplit(v, h, lo);
    g_Wt[f * 2048 + k]        = h;
    g_Wt[f * 2048 + 1024 + k] = lo;
}

// ---------------------------------------------------------------------------
// Kernel C: fused pair GEMM via HMMA, 3-term bf16 split.
// Issue order tuned: term-outer MMA loops maximize same-accumulator distance
// (asm volatile issues in program order; distance-1 chains stalled R10).
// ---------------------------------------------------------------------------
#define OFF_LH 0u
#define OFF_LL 69632u
#define OFF_RH 139264u
#define OFF_RL 174080u
#define OFF_A2H 0u
#define OFF_A2L 66048u
#define WBUF    132096u
#define SMEM_SZ 208896

__global__ __launch_bounds__(512, 1) void pair_kernel(
    const float* __restrict__ bias, float* __restrict__ out)
{
    extern __shared__ char smem[];
    uint32_t sb = smem_u32(smem);
    int t = threadIdx.x, lane = t & 31, w = t >> 5;
    int gi0 = blockIdx.y * 8;
    int gj0 = blockIdx.x * 4;

    // ---- load L (256 rows) and R (128 rows) split tiles into padded smem ----
    {
        const char* Lg = (const char*)g_Lsp + (size_t)(gi0 * 32) * 512;
#pragma unroll
        for (int it = 0; it < 16; it++) {
            int v = it * 512 + t, r = v >> 5, s = v & 31;
            uint4 x = *(const uint4*)(Lg + (size_t)r * 512 + s * 16);
            *(uint4*)(smem + (s < 16 ? OFF_LH : OFF_LL) + r * 272 + (s & 15) * 16) = x;
        }
        const char* Rg = (const char*)g_Rsp + (size_t)(gj0 * 32) * 512;
#pragma unroll
        for (int it = 0; it < 8; it++) {
            int v = it * 512 + t, r = v >> 5, s = v & 31;
            uint4 x = *(const uint4*)(Rg + (size_t)r * 512 + s * 16);
            *(uint4*)(smem + (s < 16 ? OFF_RH : OFF_RL) + r * 272 + (s & 15) * 16) = x;
        }
    }
    __syncthreads();

    // ---- Phase 1: warp tile M=64 (wm) x N=32 (wn) ----
    int wm = w >> 2, wn = w & 3;
    float D[4][4][4];
#pragma unroll
    for (int a = 0; a < 4; a++)
#pragma unroll
        for (int b = 0; b < 4; b++)
#pragma unroll
            for (int c = 0; c < 4; c++) D[a][b][c] = 0.f;

    uint32_t aRowH = sb + OFF_LH + (wm * 64 + (lane & 15)) * 272 + ((lane >> 4) & 1) * 16;
    uint32_t aRowL = sb + OFF_LL + (wm * 64 + (lane & 15)) * 272 + ((lane >> 4) & 1) * 16;
    uint32_t bRowH = sb + OFF_RH + (wn * 32 + (lane & 15)) * 272 + ((lane >> 4) & 1) * 16;
    uint32_t bRowL = sb + OFF_RL + (wn * 32 + (lane & 15)) * 272 + ((lane >> 4) & 1) * 16;

#pragma unroll
    for (int kk = 0; kk < 8; kk++) {
        uint32_t ko = kk * 32;
        uint32_t ah[4][4], al[4][4], bh[2][4], bl[2][4];
#pragma unroll
        for (int mt = 0; mt < 4; mt++) {
            ldsm_x4(ah[mt], aRowH + mt * 16 * 272 + ko);
            ldsm_x4(al[mt], aRowL + mt * 16 * 272 + ko);
        }
#pragma unroll
        for (int g = 0; g < 2; g++) {
            ldsm_x4(bh[g], bRowH + g * 16 * 272 + ko);
            ldsm_x4(bl[g], bRowL + g * 16 * 272 + ko);
        }
        // term 1: ah x bh   (same-accumulator distance = 16)
#pragma unroll
        for (int g = 0; g < 2; g++)
#pragma unroll
            for (int s2 = 0; s2 < 2; s2++) {
                int nt = g * 2 + s2;
#pragma unroll
                for (int mt = 0; mt < 4; mt++)
                    mma2(D[mt][nt], ah[mt], bh[g][s2], bh[g][s2 + 2]);
            }
        // term 2: al x bh
#pragma unroll
        for (int g = 0; g < 2; g++)
#pragma unroll
            for (int s2 = 0; s2 < 2; s2++) {
                int nt = g * 2 + s2;
#pragma unroll
                for (int mt = 0; mt < 4; mt++)
                    mma2(D[mt][nt], al[mt], bh[g][s2], bh[g][s2 + 2]);
            }
        // term 3: ah x bl
#pragma unroll
        for (int g = 0; g < 2; g++)
#pragma unroll
            for (int s2 = 0; s2 < 2; s2++) {
                int nt = g * 2 + s2;
#pragma unroll
                for (int mt = 0; mt < 4; mt++)
                    mma2(D[mt][nt], ah[mt], bl[g][s2], bl[g][s2 + 2]);
            }
    }
    __syncthreads();   // all warps done reading L/R smem before overwrite

    // ---- Phase 1.5: split accumulators -> A2h / A2l ----
#pragma unroll
    for (int mt = 0; mt < 4; mt++)
#pragma unroll
        for (int nt = 0; nt < 4; nt++)
#pragma unroll
            for (int rr = 0; rr < 2; rr++) {
                int idl = wm * 64 + mt * 16 + (lane >> 2) + rr * 8;
                int p = (idl >> 5) * 4 + wn;
                int d = idl & 31;
                int e = nt * 8 + (lane & 3) * 2;
                uint32_t ofs = (uint32_t)p * 2064 + (uint32_t)(d * 32 + e) * 2;
                __nv_bfloat16 h0, l0, h1, l1;
                bsplit(D[mt][nt][rr * 2 + 0], h0, l0);
                bsplit(D[mt][nt][rr * 2 + 1], h1, l1);
                __nv_bfloat162 ph; ph.x = h0; ph.y = h1;
                __nv_bfloat162 pl; pl.x = l0; pl.y = l1;
                *(__nv_bfloat162*)(smem + OFF_A2H + ofs) = ph;
                *(__nv_bfloat162*)(smem + OFF_A2L + ofs) = pl;
            }
    __syncthreads();

    // ---- Phase 2: warp = fg (f-group of 32) x ks (K-quarter) ----
    int fg = w & 3, ks = w >> 2;
    float D2[2][4][4];
#pragma unroll
    for (int a = 0; a < 2; a++)
#pragma unroll
        for (int b = 0; b < 4; b++)
#pragma unroll
            for (int c = 0; c < 4; c++) D2[a][b][c] = 0.f;

    uint32_t a2RowH = sb + OFF_A2H + (lane & 15) * 2064 + ((lane >> 4) & 1) * 16;
    uint32_t a2RowL = sb + OFF_A2L + (lane & 15) * 2064 + ((lane >> 4) & 1) * 16;
    const char* Wg = (const char*)g_Wt;

    auto copyW = [&](int kc, int bsel) {
        uint32_t wb = sb + WBUF + (uint32_t)bsel * 36864;
#pragma unroll
        for (int it = 0; it < 4; it++) {
            int v = it * 512 + t;
            int half = v >> 10, v2 = v & 1023, f = v2 >> 3, s = v2 & 7;
            cpa16(wb + half * 18432 + f * 144 + s * 16,
                  Wg + (size_t)f * 4096 + half * 2048 + kc * 128 + s * 16);
        }
    };

    copyW(0, 0); CPA_COMMIT();
    for (int kc = 0; kc < 16; kc++) {
        if (kc < 15) { copyW(kc + 1, (kc + 1) & 1); CPA_COMMIT(); CPA_WAIT1(); }
        else         { CPA_WAIT0(); }
        __syncthreads();   // chunk kc visible; prev compute done

        uint32_t koA = (uint32_t)kc * 128 + ks * 32;
        uint32_t a2h0[4], a2h1[4], a2l0[4], a2l1[4];
        ldsm_x4(a2h0, a2RowH + koA);
        ldsm_x4(a2h1, a2RowH + 16 * 2064 + koA);
        ldsm_x4(a2l0, a2RowL + koA);
        ldsm_x4(a2l1, a2RowL + 16 * 2064 + koA);

        uint32_t wrH = sb + WBUF + (uint32_t)(kc & 1) * 36864
                     + (fg * 32 + (lane & 15)) * 144 + ((lane >> 4) & 1) * 16
                     + ks * 32;
        uint32_t wrL = wrH + 18432;
        uint32_t whq[2][4], wlq[2][4];
        ldsm_x4(whq[0], wrH);
        ldsm_x4(whq[1], wrH + 16 * 144);
        ldsm_x4(wlq[0], wrL);
        ldsm_x4(wlq[1], wrL + 16 * 144);

        // term 1: a2h x wh  (same-accumulator distance = 8)
#pragma unroll
        for (int g = 0; g < 2; g++)
#pragma unroll
            for (int s2 = 0; s2 < 2; s2++) {
                int nt = g * 2 + s2;
                mma2(D2[0][nt], a2h0, whq[g][s2], whq[g][s2 + 2]);
                mma2(D2[1][nt], a2h1, whq[g][s2], whq[g][s2 + 2]);
            }
        // term 2: a2l x wh
#pragma unroll
        for (int g = 0; g < 2; g++)
#pragma unroll
            for (int s2 = 0; s2 < 2; s2++) {
                int nt = g * 2 + s2;
                mma2(D2[0][nt], a2l0, whq[g][s2], whq[g][s2 + 2]);
                mma2(D2[1][nt], a2l1, whq[g][s2], whq[g][s2 + 2]);
            }
        // term 3: a2h x wl
#pragma unroll
        for (int g = 0; g < 2; g++)
#pragma unroll
            for (int s2 = 0; s2 < 2; s2++) {
                int nt = g * 2 + s2;
                mma2(D2[0][nt], a2h0, wlq[g][s2], wlq[g][s2 + 2]);
                mma2(D2[1][nt], a2h1, wlq[g][s2], wlq[g][s2 + 2]);
            }
        __syncthreads();   // all warps done with buf[kc&1] before overwrite
    }

    // ---- K-reduction (4-way) via smem, then epilogue ----
    float* rbuf = (float*)smem;
#pragma unroll
    for (int pm = 0; pm < 2; pm++)
#pragma unroll
        for (int nt = 0; nt < 4; nt++)
#pragma unroll
            for (int rr = 0; rr < 2; rr++) {
                int p  = pm * 16 + (lane >> 2) + rr * 8;
                int fl = nt * 8 + (lane & 3) * 2;
                float2 v;
                v.x = D2[pm][nt][rr * 2 + 0];
                v.y = D2[pm][nt][rr * 2 + 1];
                *(float2*)(rbuf + w * 1160 + p * 36 + fl) = v;
            }
    __syncthreads();

    {
        int p = t >> 4, fb = (t & 15) * 8;
        int fgr = fb >> 5, fi = fb & 31;
        float4 s0 = make_float4(0.f, 0.f, 0.f, 0.f);
        float4 s1 = make_float4(0.f, 0.f, 0.f, 0.f);
#pragma unroll
        for (int kq = 0; kq < 4; kq++) {
            const float* bp2 = rbuf + (kq * 4 + fgr) * 1160 + p * 36 + fi;
            float4 v0 = *(const float4*)bp2;
            float4 v1 = *(const float4*)(bp2 + 4);
            s0.x += v0.x; s0.y += v0.y; s0.z += v0.z; s0.w += v0.w;
            s1.x += v1.x; s1.y += v1.y; s1.z += v1.z; s1.w += v1.w;
        }
        int gi = gi0 + (p >> 2), gj = gj0 + (p & 3);
        float inv = 1.f / (g_norm[gi * I_DIM + gj] + 0.001f);
        float4 b0 = *(const float4*)(bias + fb);
        float4 b1 = *(const float4*)(bias + fb + 4);
        float* orow = out + (size_t)(gi * I_DIM + gj) * OD + fb;
        *(float4*)(orow)     = make_float4((s0.x + b0.x) * inv, (s0.y + b0.y) * inv,
                                           (s0.z + b0.z) * inv, (s0.w + b0.w) * inv);
        *(float4*)(orow + 4) = make_float4((s1.x + b1.x) * inv, (s1.y + b1.y) * inv,
                                           (s1.z + b1.z) * inv, (s1.w + b1.w) * inv);
    }
}

// ---------------------------------------------------------------------------
extern "C" void kernel_launch(void* const* d_in, const int* in_sizes, int n_in,
                              void* d_out, int out_size)
{
    const float* node = (const float*)d_in[0];
    const float* mask = (const float*)d_in[1];
    const float* Wp   = (const float*)d_in[2];
    const float* bp   = (const float*)d_in[3];
    const float* W2   = (const float*)d_in[4];
    const float* bias = (const float*)d_in[5];
    float* out = (float*)d_out;

    cudaFuncSetAttribute(ln_proj_kernel, cudaFuncAttributeMaxDynamicSharedMemorySize, 74752);
    cudaFuncSetAttribute(pair_kernel,    cudaFuncAttributeMaxDynamicSharedMemorySize, SMEM_SZ);

    ln_proj_kernel<<<6144, 256, 74752>>>(node, mask, Wp, bp);
    norm_kernel<<<576, 256>>>(mask);
    wprep_kernel<<<512, 256>>>(W2);
    pair_kernel<<<dim3(96, 48), 512, SMEM_SZ>>>(bias, out);
}